// round 7
// baseline (speedup 1.0000x reference)
#include <cuda_runtime.h>

#define NCLS 19
#define HW_   (512*1024)        // 2^19
#define NPIX  (4*HW_)           // 2,097,152
#define NPIX4 (NPIX/4)          // 524,288
#define GRIDP 296               // 2 CTAs/SM * 148 SMs -> co-resident at 128 regs
#define TB    256
#define VPT   7                 // 296*256*7 = 530,432 >= NPIX4 (only quad 6 needs check)
#define INV   0xFFFFFFFFu

// ---- static scratch (zero-initialized at load; self-cleaned each call) ----
__device__ unsigned g_hist0[4096];
__device__ unsigned g_hist1[4096];
__device__ unsigned g_cnt2[256];
__device__ float    g_sum2[256];
__device__ double   g_sumHi;
__device__ unsigned g_cntHi;
__device__ unsigned g_pref0p1, g_pref01p1, g_k1, g_k2;   // prefix+1; 0 = invalid
__device__ unsigned g_done0, g_done1, g_done2, g_flag0, g_flag1;

// ------------------------------------------------------------------
// Descending scan over a 4096-bin histogram; winning thread writes the
// (bin, rank) into shared outputs. 256 threads, 16 bins each.
__device__ void scan4096(const unsigned* __restrict__ hist, unsigned k,
                         unsigned* ss, unsigned* out_bin, unsigned* out_r,
                         bool derive_k) {
    int t = threadIdx.x;
    unsigned cnt[16]; unsigned myv = 0;
    #pragma unroll
    for (int i = 0; i < 16; i++) { cnt[i] = __ldcg(&hist[4095 - (t * 16 + i)]); myv += cnt[i]; }
    ss[t] = myv; __syncthreads();
    for (int off = 1; off < 256; off <<= 1) {
        unsigned x = (t >= off) ? ss[t - off] : 0u;
        __syncthreads(); ss[t] += x; __syncthreads();
    }
    if (derive_k) {
        unsigned total = ss[255];          // uniform
        if (total == 0) return;            // *out_bin stays INV
        unsigned nk = (unsigned)(0.7f * (float)total);
        if (nk < 100000u) nk = 100000u;
        if (nk > total)   nk = total;
        k = nk;
    }
    unsigned hi = ss[t], lo = hi - myv;
    if (k > lo && k <= hi) {               // exactly one thread wins
        unsigned cum = lo;
        #pragma unroll
        for (int i = 0; i < 16; i++) {
            cum += cnt[i];
            if (k <= cum) {
                *out_bin = 4095u - (t * 16 + i);
                *out_r   = k - (cum - cnt[i]);
                break;
            }
        }
    }
}

// ------------------------------------------------------------------
// One pixel-quad NLL: 19 float4 streaming loads + 4 scalar target loads.
__device__ __forceinline__ uint4 quad_nll(const float* __restrict__ logits,
                                          const longlong2* __restrict__ t64,
                                          const int4* __restrict__ t32,
                                          int tmode, int q) {
    int p  = q << 2;
    int n  = p >> 19;
    int hw = p & (HW_ - 1);
    const float*  rowb = logits + (size_t)n * (NCLS * (size_t)HW_) + hw;
    const float4* base = (const float4*)rowb;
    int t0, t1, t2, t3;
    if (tmode) {
        longlong2 ta = __ldg(t64 + 2 * q);
        longlong2 tb = __ldg(t64 + 2 * q + 1);
        t0 = (int)ta.x; t1 = (int)ta.y; t2 = (int)tb.x; t3 = (int)tb.y;
    } else {
        int4 tt = __ldg(t32 + q);
        t0 = tt.x; t1 = tt.y; t2 = tt.z; t3 = tt.w;
    }
    // scalar target gathers (same lines as the stream -> L2 hits)
    float x0 = __ldg(rowb + (size_t)t0 * HW_ + 0);
    float x1 = __ldg(rowb + (size_t)t1 * HW_ + 1);
    float x2 = __ldg(rowb + (size_t)t2 * HW_ + 2);
    float x3 = __ldg(rowb + (size_t)t3 * HW_ + 3);

    float s0 = 0.f, s1 = 0.f, s2 = 0.f, s3 = 0.f;
    #pragma unroll
    for (int c = 0; c < NCLS; c++) {
        float4 w = __ldg(base + (size_t)c * (HW_ / 4));
        s0 += __expf(w.x); s1 += __expf(w.y); s2 += __expf(w.z); s3 += __expf(w.w);
    }
    float l0 = __logf(s0) - x0, l1 = __logf(s1) - x1;
    float l2 = __logf(s2) - x2, l3 = __logf(s3) - x3;
    return make_uint4(__float_as_uint(l0), __float_as_uint(l1),
                      __float_as_uint(l2), __float_as_uint(l3));
}

// ------------------------------------------------------------------
// Single persistent kernel: NLL in registers -> hist0 -> scan0 -> hist1 ->
// scan1 -> byte phase -> final mean -> self-clean. Spin grid barriers.
__global__ void __launch_bounds__(TB, 2) k_ohem(const float* __restrict__ logits,
                                                const void* __restrict__ tgt_raw,
                                                float* __restrict__ out) {
    __shared__ unsigned sh[4096];       // hist staging / byte-phase cnt+sum
    __shared__ unsigned s_ss[256];
    __shared__ double   s_rd[256];
    __shared__ unsigned s_rc[256];
    __shared__ unsigned s_bin, s_r;
    __shared__ bool     s_last;

    int t = threadIdx.x;
    for (int i = t; i < 4096; i += TB) sh[i] = 0;
    __syncthreads();

    // ---- dtype detection (uniform; 8 cached loads) ----
    const long long* tdet = (const long long*)tgt_raw;
    int tmode = 1;
    #pragma unroll
    for (int i = 0; i < 8; i++) {
        long long x = tdet[i];
        if (x < 0 || x >= (long long)NCLS) tmode = 0;
    }
    const longlong2* t64 = (const longlong2*)tgt_raw;
    const int4*      t32 = (const int4*)tgt_raw;

    // ---- Phase A: losses into registers + shared hist0 ----
    uint4 v[VPT];
    const int stride = GRIDP * TB;
    const int q0 = blockIdx.x * TB + t;
    const bool ok6 = (q0 + 6 * stride) < NPIX4;

    #pragma unroll
    for (int i = 0; i < 6; i++)                 // always in range
        v[i] = quad_nll(logits, t64, t32, tmode, q0 + i * stride);
    v[6] = ok6 ? quad_nll(logits, t64, t32, tmode, q0 + 6 * stride)
               : make_uint4(0, 0, 0, 0);

    #pragma unroll
    for (int i = 0; i < VPT; i++) {
        if ((int)v[i].x > 0) atomicAdd(&sh[v[i].x >> 20], 1u);
        if ((int)v[i].y > 0) atomicAdd(&sh[v[i].y >> 20], 1u);
        if ((int)v[i].z > 0) atomicAdd(&sh[v[i].z >> 20], 1u);
        if ((int)v[i].w > 0) atomicAdd(&sh[v[i].w >> 20], 1u);
    }
    __syncthreads();
    for (int i = t; i < 4096; i += TB) {
        unsigned c = sh[i];
        if (c) atomicAdd(&g_hist0[i], c);
    }
    __threadfence();
    __syncthreads();                       // all hist0 atomics issued
    if (t == 0) s_last = (atomicAdd(&g_done0, 1u) == GRIDP - 1);
    __syncthreads();

    // re-zero sh for hist1 while waiting
    for (int i = t; i < 4096; i += TB) sh[i] = 0;

    // ---- scan0 by last-arriving block ----
    if (s_last) {
        if (t == 0) { s_bin = INV; s_r = 0; }
        __syncthreads();
        scan4096(g_hist0, 0, s_ss, &s_bin, &s_r, true);
        __syncthreads();
        if (t == 0) {
            if (s_bin != INV) { g_pref0p1 = s_bin + 1u; g_k1 = s_r; }
            __threadfence();
            atomicExch(&g_flag0, 1u);
        }
    }
    if (t == 0) { while (*(volatile unsigned*)&g_flag0 == 0u) __nanosleep(64); }
    __syncthreads();
    __threadfence();
    unsigned p0p1 = *(volatile unsigned*)&g_pref0p1;

    // ---- hist1 from registers ----
    if (p0p1 != 0u) {
        unsigned pref0 = p0p1 - 1u;
        #pragma unroll
        for (int i = 0; i < VPT; i++) {
            unsigned b;
            b = v[i].x; if ((int)b > 0 && (b >> 20) == pref0) atomicAdd(&sh[(b >> 8) & 0xFFFu], 1u);
            b = v[i].y; if ((int)b > 0 && (b >> 20) == pref0) atomicAdd(&sh[(b >> 8) & 0xFFFu], 1u);
            b = v[i].z; if ((int)b > 0 && (b >> 20) == pref0) atomicAdd(&sh[(b >> 8) & 0xFFFu], 1u);
            b = v[i].w; if ((int)b > 0 && (b >> 20) == pref0) atomicAdd(&sh[(b >> 8) & 0xFFFu], 1u);
        }
        __syncthreads();
        for (int i = t; i < 4096; i += TB) {
            unsigned c = sh[i];
            if (c) atomicAdd(&g_hist1[i], c);
        }
    }
    __threadfence();
    __syncthreads();                       // all hist1 atomics issued
    if (t == 0) s_last = (atomicAdd(&g_done1, 1u) == GRIDP - 1);
    __syncthreads();

    // ---- scan1 by last-arriving block ----
    if (s_last) {
        if (t == 0) { s_bin = INV; s_r = 0; }
        __syncthreads();
        if (p0p1 != 0u) {
            scan4096(g_hist1, __ldcg(&g_k1), s_ss, &s_bin, &s_r, false);
            __syncthreads();
        }
        if (t == 0) {
            if (p0p1 != 0u && s_bin != INV) {
                g_pref01p1 = ((((p0p1 - 1u) << 12) | s_bin)) + 1u;
                g_k2 = s_r;
            }
            __threadfence();
            atomicExch(&g_flag1, 1u);
        }
    }
    if (t == 0) { while (*(volatile unsigned*)&g_flag1 == 0u) __nanosleep(64); }
    __syncthreads();
    __threadfence();
    unsigned p01p1 = *(volatile unsigned*)&g_pref01p1;

    // ---- byte-level phase from registers ----
    unsigned* s_cnt2 = sh;                    // [0..255]
    float*    s_fs2  = (float*)(sh + 256);    // [256..511]
    for (int i = t; i < 256; i += TB) { s_cnt2[i] = 0; s_fs2[i] = 0.f; }
    __syncthreads();

    float    fHi = 0.f;                       // <=28 exact float adds
    unsigned cHi = 0;
    if (p01p1 != 0u) {
        unsigned pref01 = p01p1 - 1u;
        #pragma unroll
        for (int i = 0; i < VPT; i++) {
            #pragma unroll
            for (int j = 0; j < 4; j++) {
                unsigned bb = (j == 0) ? v[i].x : (j == 1) ? v[i].y : (j == 2) ? v[i].z : v[i].w;
                if ((int)bb > 0) {
                    unsigned p24 = bb >> 8;
                    if (p24 > pref01) { fHi += __uint_as_float(bb); cHi++; }
                    else if (p24 == pref01) {
                        atomicAdd(&s_cnt2[bb & 0xFFu], 1u);
                        atomicAdd(&s_fs2[bb & 0xFFu], __uint_as_float(bb));
                    }
                }
            }
        }
    } else {
        // no valid pixels: plain mean over everything
        #pragma unroll
        for (int i = 0; i < VPT; i++) {
            fHi += __uint_as_float(v[i].x) + __uint_as_float(v[i].y)
                 + __uint_as_float(v[i].z) + __uint_as_float(v[i].w);
        }
    }

    s_rd[t] = (double)fHi; s_rc[t] = cHi;
    __syncthreads();
    for (int off = 128; off > 0; off >>= 1) {
        if (t < off) { s_rd[t] += s_rd[t + off]; s_rc[t] += s_rc[t + off]; }
        __syncthreads();
    }
    if (t == 0) {
        atomicAdd(&g_sumHi, s_rd[0]);
        if (s_rc[0]) atomicAdd(&g_cntHi, s_rc[0]);
    }
    for (int i = t; i < 256; i += TB) {
        if (s_cnt2[i]) { atomicAdd(&g_cnt2[i], s_cnt2[i]); atomicAdd(&g_sum2[i], s_fs2[i]); }
    }
    __threadfence();
    __syncthreads();                       // all byte-phase atomics issued
    if (t == 0) s_last = (atomicAdd(&g_done2, 1u) == GRIDP - 1);
    __syncthreads();
    if (!s_last) return;

    // ---- final mean (last block only) ----
    if (t == 0) {
        double outv;
        if (p01p1 == 0u) {
            outv = __ldcg(&g_sumHi) / (double)NPIX;
        } else {
            unsigned k2 = __ldcg(&g_k2);
            unsigned cum = 0;
            double ssum = 0.0;
            for (int b = 255; b >= 0; b--) {
                unsigned c = __ldcg(&g_cnt2[b]);
                ssum += (double)__ldcg(&g_sum2[b]);
                cum  += c;
                if (cum >= k2) break;            // threshold byte reached (ties kept)
            }
            double   ktot = __ldcg(&g_sumHi) + ssum;
            unsigned kcnt = __ldcg(&g_cntHi) + cum;
            if (kcnt == 0) kcnt = 1;
            outv = ktot / (double)kcnt;
        }
        out[0] = (float)outv;
    }
    __syncthreads();

    // ---- self-clean for next graph replay (all other blocks have exited
    //      past every flag/counter read) ----
    for (int i = t; i < 4096; i += TB) { g_hist0[i] = 0; g_hist1[i] = 0; }
    for (int i = t; i < 256;  i += TB) { g_cnt2[i] = 0; g_sum2[i] = 0.f; }
    if (t == 0) {
        g_sumHi = 0.0; g_cntHi = 0;
        g_pref0p1 = 0; g_pref01p1 = 0; g_k1 = 0; g_k2 = 0;
        g_done0 = 0; g_done1 = 0; g_done2 = 0;
        g_flag0 = 0; g_flag1 = 0;
        __threadfence();
    }
}

// ------------------------------------------------------------------
extern "C" void kernel_launch(void* const* d_in, const int* in_sizes, int n_in,
                              void* d_out, int out_size) {
    const float* logits = (const float*)d_in[0];
    const void*  tgt    = d_in[1];
    float* out = (float*)d_out;

    k_ohem<<<GRIDP, TB>>>(logits, tgt, out);
}